// round 7
// baseline (speedup 1.0000x reference)
#include <cuda_runtime.h>
#include <cuda_bf16.h>
#include <cuda_fp16.h>
#include <mma.h>
#include <cstdint>

using namespace nvcuda;

// Problem constants (fixed by setup_inputs)
#define BB 8
#define HH 64
#define WW 64
#define TT 4096          // HH*WW
#define CC 768
#define MM (BB * TT)     // 32768
#define ELEMS (BB * TT * CC)
#define SEG 64
#define NSEG 64
#define LANES (BB * CC)  // 6144

// Shift table (24 groups of 32 channels)
__constant__ int c_dy[24] = {0, 0, 1, -1, 1, -1, 1, -1, 0, 0, 2, -2, 2, -2, 2, -2, 2, 1, 2, 1, -2, -1, -2, -1};
__constant__ int c_dx[24] = {1, -1, 0, 0, 1, -1, -1, 1, 2, -2, 0, 0, 2, -2, -2, 2, 1, 2, -1, -2, 1, 2, -1, -2};

// Scratch buffers (no cudaMalloc allowed)
__device__ __half g_xsh[ELEMS];
__device__ __half g_prod[ELEMS];
__device__ __half g_w[4][CC * CC];
__device__ float  g_k[ELEMS];
__device__ __half g_v[ELEMS];
__device__ __half g_sr[ELEMS];
__device__ __half g_v1[ELEMS];
__device__ __half g_vf[ELEMS];
// WKV segment summaries + carry-in states
__device__ float g_sp[NSEG][LANES];
__device__ float g_sq[NSEG][LANES];
__device__ float g_so[NSEG][LANES];
__device__ float g_cp[NSEG][LANES];
__device__ float g_cq[NSEG][LANES];
__device__ float g_co[NSEG][LANES];

__device__ __forceinline__ int zig(int t) {
    int r = t >> 6, j = t & 63;
    return (r << 6) + ((r & 1) ? (63 - j) : j);
}

__device__ __forceinline__ void store_h4(__half* dst, float4 v) {
    __half2 a = __floats2half2_rn(v.x, v.y);
    __half2 b = __floats2half2_rn(v.z, v.w);
    *(uint2*)dst = make_uint2(*(unsigned*)&a, *(unsigned*)&b);
}

// ---------------------------------------------------------------------------
// 1) shift (mul_shift) + zigzag reorder + f32->f16 convert, fused gather.
// ---------------------------------------------------------------------------
__global__ void shift_gather_kernel(const float* __restrict__ x, __half* __restrict__ xs)
{
    int gid = blockIdx.x * blockDim.x + threadIdx.x;       // over B*T*(C/4)
    const int CV = CC / 4;
    if (gid >= BB * TT * CV) return;
    int cv = gid % CV;
    int bt = gid / CV;
    int t  = bt % TT;
    int b  = bt / TT;
    int c  = cv * 4;

    int r   = t >> 6;
    int j   = t & 63;
    int col = (r & 1) ? (63 - j) : j;                      // order[t] = (r, col)

    int g   = c >> 5;
    int srow = r - c_dy[g];
    int scol = col - c_dx[g];

    float4 val = make_float4(0.f, 0.f, 0.f, 0.f);
    if ((unsigned)srow < (unsigned)HH && (unsigned)scol < (unsigned)WW) {
        val = *(const float4*)&x[((size_t)b * TT + srow * WW + scol) * CC + c];
    }
    store_h4(&xs[((size_t)b * TT + t) * CC + c], val);
}

// ---------------------------------------------------------------------------
// weight convert: 4 weight matrices f32 -> f16 in one launch
// ---------------------------------------------------------------------------
__global__ void wconv4_kernel(const float* __restrict__ w0, const float* __restrict__ w1,
                              const float* __restrict__ w2, const float* __restrict__ w3,
                              __half* __restrict__ wh)
{
    const int n4 = CC * CC / 4;
    int gid = blockIdx.x * blockDim.x + threadIdx.x;
    if (gid >= 4 * n4) return;
    int which = gid / n4;
    int idx   = gid % n4;
    const float* w = (which == 0) ? w0 : (which == 1) ? w1 : (which == 2) ? w2 : w3;
    store_h4(&wh[(size_t)gid * 4], ((const float4*)w)[idx]);
}

// ---------------------------------------------------------------------------
// elementwise multiply fp16: prod = sr .* vf
// ---------------------------------------------------------------------------
__global__ void ewmul_kernel(const __half* __restrict__ a, const __half* __restrict__ b,
                             __half* __restrict__ o)
{
    int gid = blockIdx.x * blockDim.x + threadIdx.x;       // over ELEMS/8
    if (gid >= ELEMS / 8) return;
    uint4 va = ((const uint4*)a)[gid];
    uint4 vb = ((const uint4*)b)[gid];
    __half2* pa = (__half2*)&va;
    __half2* pb = (__half2*)&vb;
    uint4 vo;
    __half2* po = (__half2*)&vo;
#pragma unroll
    for (int i = 0; i < 4; i++) {
        float2 fa = __half22float2(pa[i]);
        float2 fb = __half22float2(pb[i]);
        po[i] = __floats2half2_rn(fa.x * fb.x, fa.y * fb.y);
    }
    ((uint4*)o)[gid] = vo;
}

// ---------------------------------------------------------------------------
// cp.async helpers
// ---------------------------------------------------------------------------
__device__ __forceinline__ void cp_async16(void* smem, const void* gmem) {
    unsigned int s = (unsigned int)__cvta_generic_to_shared(smem);
    asm volatile("cp.async.cg.shared.global [%0], [%1], 16;\n" :: "r"(s), "l"(gmem));
}
__device__ __forceinline__ void cp_commit() { asm volatile("cp.async.commit_group;\n" ::: "memory"); }
template<int N> __device__ __forceinline__ void cp_wait() { asm volatile("cp.async.wait_group %0;\n" :: "n"(N) : "memory"); }

// ---------------------------------------------------------------------------
// 2) fp16 tensor-core GEMM, 3-stage cp.async pipeline.
//    C[m,n] = sum_k A[m,k] * W[n,k].  BM=128 BN=128 BK=32, 256 thr, 8 warps
//    (4x2), warp tile 32x64, 16x16x16 half frags, f32 accum.
//    EPI: 0 none, 1 sigmoid.  OutT: float (direct) or __half (smem-staged).
// ---------------------------------------------------------------------------
template <int EPI, typename OutT>
__global__ __launch_bounds__(256)
void gemm_fp16_kernel(const __half* __restrict__ A, const __half* __restrict__ Wt,
                      OutT* __restrict__ Co)
{
    constexpr int BM = 128, BN = 128, BK = 32, PAD = 8, STAGES = 3;
    constexpr int LD = BK + PAD;                            // 40 halfs
    constexpr int K = CC, N = CC;
    constexpr int NIT = K / BK;                             // 24

    extern __shared__ char dsm[];
    __half* Asb = (__half*)dsm;                             // STAGES*BM*LD
    __half* Bsb = (__half*)(dsm + STAGES * BM * LD * 2);
    float*  stg = (float*)dsm;                              // epilogue reuse: 128 x 132

    const int m0 = blockIdx.y * BM;
    const int n0 = blockIdx.x * BN;
    const int tid = threadIdx.x;
    const int warp = tid >> 5;
    const int wm = warp >> 1;                               // 0..3 -> 32-row slab
    const int wn = warp & 1;                                // 0..1 -> 64-col slab

    wmma::fragment<wmma::accumulator, 16, 16, 16, float> cf[2][4];
#pragma unroll
    for (int i = 0; i < 2; i++)
#pragma unroll
        for (int jn = 0; jn < 4; jn++)
            wmma::fill_fragment(cf[i][jn], 0.f);

    // loader: A tile 128x32 halfs = 256 x 16B chunks; 2 per thread (A) + 2 (B)
    auto issue_loads = [&](int st, int k0) {
        int row = tid >> 1;                                 // 0..127
        int c8  = (tid & 1) * 8;                            // 0 or 8 (halfs)
        __half* as = Asb + st * BM * LD + row * LD;
        __half* bs = Bsb + st * BM * LD + row * LD;
        const __half* ag = &A[(size_t)(m0 + row) * K + k0];
        const __half* bg = &Wt[(size_t)(n0 + row) * K + k0];
        cp_async16(as + c8,      ag + c8);
        cp_async16(bs + c8,      bg + c8);
        cp_async16(as + c8 + 16, ag + c8 + 16);
        cp_async16(bs + c8 + 16, bg + c8 + 16);
    };

    // prologue: stages 0,1
    issue_loads(0, 0);
    cp_commit();
    issue_loads(1, BK);
    cp_commit();

    for (int ch = 0; ch < NIT; ch++) {
        const int st = ch % 3;
        if (ch + 2 < NIT) {
            issue_loads((ch + 2) % 3, (ch + 2) * BK);
            cp_commit();
            cp_wait<2>();
        } else if (ch + 1 < NIT) {
            cp_wait<1>();
        } else {
            cp_wait<0>();
        }
        __syncthreads();

        const __half* as = Asb + st * BM * LD;
        const __half* bs = Bsb + st * BM * LD;
#pragma unroll
        for (int kk = 0; kk < BK; kk += 16) {
            wmma::fragment<wmma::matrix_a, 16, 16, 16, __half, wmma::row_major> af[2];
            wmma::fragment<wmma::matrix_b, 16, 16, 16, __half, wmma::col_major> bf[4];
#pragma unroll
            for (int i = 0; i < 2; i++)
                wmma::load_matrix_sync(af[i], as + (wm * 32 + i * 16) * LD + kk, LD);
#pragma unroll
            for (int jn = 0; jn < 4; jn++)
                wmma::load_matrix_sync(bf[jn], bs + (wn * 64 + jn * 16) * LD + kk, LD);
#pragma unroll
            for (int i = 0; i < 2; i++)
#pragma unroll
                for (int jn = 0; jn < 4; jn++)
                    wmma::mma_sync(cf[i][jn], af[i], bf[jn], cf[i][jn]);
        }
        __syncthreads();         // protect stage about to be overwritten
    }

    // epilogue
    if (EPI == 1) {
#pragma unroll
        for (int i = 0; i < 2; i++)
#pragma unroll
            for (int jn = 0; jn < 4; jn++)
#pragma unroll
                for (int e = 0; e < cf[i][jn].num_elements; e++)
                    cf[i][jn].x[e] = 1.f / (1.f + __expf(-cf[i][jn].x[e]));
    }

    if constexpr (sizeof(OutT) == 4) {
        // direct f32 store
#pragma unroll
        for (int i = 0; i < 2; i++)
#pragma unroll
            for (int jn = 0; jn < 4; jn++)
                wmma::store_matrix_sync(
                    (float*)&Co[(size_t)(m0 + wm * 32 + i * 16) * N + n0 + wn * 64 + jn * 16],
                    cf[i][jn], N, wmma::mem_row_major);
    } else {
        // stage f32 in smem, convert to f16, vectorized global store
        constexpr int SLD = 132;
#pragma unroll
        for (int i = 0; i < 2; i++)
#pragma unroll
            for (int jn = 0; jn < 4; jn++)
                wmma::store_matrix_sync(
                    &stg[(size_t)(wm * 32 + i * 16) * SLD + wn * 64 + jn * 16],
                    cf[i][jn], SLD, wmma::mem_row_major);
        __syncthreads();
#pragma unroll
        for (int rr = 0; rr < 8; rr++) {
            int row = rr * 16 + (tid >> 4);
            int col = (tid & 15) * 8;
            const float* s = &stg[row * SLD + col];
            __half h[8];
#pragma unroll
            for (int e = 0; e < 8; e++) h[e] = __float2half(s[e]);
            *(uint4*)&Co[(size_t)(m0 + row) * N + n0 + col] = *(uint4*)h;
        }
    }
}

// ---------------------------------------------------------------------------
// 3) WKV, chunked parallel scan. k fp32, v/y fp16.
// ---------------------------------------------------------------------------
template <int PASS>
__global__ __launch_bounds__(128)
void wkv_summary_kernel(const float* __restrict__ kk, const __half* __restrict__ vv,
                        const float* __restrict__ decay)
{
    int lane = blockIdx.x * 128 + threadIdx.x;              // 0..LANES-1
    int seg  = blockIdx.y;
    int b = lane / CC;
    int c = lane % CC;
    const float w = decay[PASS * CC + c] * (1.f / (float)TT);
    const size_t base = (size_t)b * TT * CC + c;

    float p = 0.f, q = 0.f, o = -1e38f;
#pragma unroll 8
    for (int t = 0; t < SEG; t++) {
        int tt = seg * SEG + t;
        int pidx = (PASS == 0) ? tt : zig(tt);
        size_t idx = base + (size_t)pidx * CC;
        float kt = kk[idx];
        float vt = __half2float(vv[idx]);
        float wo  = w + o;
        float no2 = fmaxf(wo, kt);
        float A2  = __expf(wo - no2);
        float B2  = __expf(kt - no2);
        p = A2 * p + B2 * vt;
        q = A2 * q + B2;
        o = no2;
    }
    g_sp[seg][lane] = p;
    g_sq[seg][lane] = q;
    g_so[seg][lane] = o;
}

template <int PASS>
__global__ __launch_bounds__(128)
void wkv_scan_kernel(const float* __restrict__ decay)
{
    int lane = blockIdx.x * 128 + threadIdx.x;
    if (lane >= LANES) return;
    int c = lane % CC;
    const float w  = decay[PASS * CC + c] * (1.f / (float)TT);
    const float wL = w * (float)SEG;

    float p = 0.f, q = 0.f, o = -1e38f;
#pragma unroll
    for (int seg = 0; seg < NSEG; seg++) {
        g_cp[seg][lane] = p;
        g_cq[seg][lane] = q;
        g_co[seg][lane] = o;
        float o1 = o + wL;
        float p2 = g_sp[seg][lane];
        float q2 = g_sq[seg][lane];
        float o2 = g_so[seg][lane];
        float no = fmaxf(o1, o2);
        float e1 = __expf(o1 - no);
        float e2 = __expf(o2 - no);
        p = e1 * p + e2 * p2;
        q = e1 * q + e2 * q2;
        o = no;
    }
}

template <int PASS>
__global__ __launch_bounds__(128)
void wkv_replay_kernel(const float* __restrict__ kk, const __half* __restrict__ vv,
                       const float* __restrict__ decay, const float* __restrict__ first,
                       __half* __restrict__ yo)
{
    int lane = blockIdx.x * 128 + threadIdx.x;
    int seg  = blockIdx.y;
    int b = lane / CC;
    int c = lane % CC;
    const float invT = 1.f / (float)TT;
    const float w = decay[PASS * CC + c] * invT;
    const float u = first[PASS * CC + c] * invT;
    const size_t base = (size_t)b * TT * CC + c;

    float p = g_cp[seg][lane];
    float q = g_cq[seg][lane];
    float o = g_co[seg][lane];

#pragma unroll 8
    for (int t = 0; t < SEG; t++) {
        int tt = seg * SEG + t;
        int pidx = (PASS == 0) ? tt : zig(tt);
        size_t idx = base + (size_t)pidx * CC;
        float kt = kk[idx];
        float vt = __half2float(vv[idx]);

        float uk = u + kt;
        float no = fmaxf(o, uk);
        float Ac = __expf(o - no);
        float Bc = __expf(uk - no);
        float y  = __fdividef(Ac * p + Bc * vt, Ac * q + Bc);
        yo[idx] = __float2half(y);

        float wo  = w + o;
        float no2 = fmaxf(wo, kt);
        float A2  = __expf(wo - no2);
        float B2  = __expf(kt - no2);
        p = A2 * p + B2 * vt;
        q = A2 * q + B2;
        o = no2;
    }
}

// ---------------------------------------------------------------------------
// Launch
// ---------------------------------------------------------------------------
extern "C" void kernel_launch(void* const* d_in, const int* in_sizes, int n_in,
                              void* d_out, int out_size)
{
    const float* x    = (const float*)d_in[0];
    const float* kw   = (const float*)d_in[1];
    const float* vw   = (const float*)d_in[2];
    const float* rw   = (const float*)d_in[3];
    const float* ow   = (const float*)d_in[4];
    const float* sdec = (const float*)d_in[5];
    const float* sfst = (const float*)d_in[6];
    float* out        = (float*)d_out;

    __half *xs, *prod, *wh, *v, *sr, *v1, *vf;
    float *k;
    cudaGetSymbolAddress((void**)&xs,   g_xsh);
    cudaGetSymbolAddress((void**)&prod, g_prod);
    cudaGetSymbolAddress((void**)&wh,   g_w);
    cudaGetSymbolAddress((void**)&k,    g_k);
    cudaGetSymbolAddress((void**)&v,    g_v);
    cudaGetSymbolAddress((void**)&sr,   g_sr);
    cudaGetSymbolAddress((void**)&v1,   g_v1);
    cudaGetSymbolAddress((void**)&vf,   g_vf);

    constexpr int DS = 128 * 132 * 4;   // >= 3-stage pipeline footprint (61440)
    cudaFuncSetAttribute(gemm_fp16_kernel<0, float>,  cudaFuncAttributeMaxDynamicSharedMemorySize, DS);
    cudaFuncSetAttribute(gemm_fp16_kernel<0, __half>, cudaFuncAttributeMaxDynamicSharedMemorySize, DS);
    cudaFuncSetAttribute(gemm_fp16_kernel<1, __half>, cudaFuncAttributeMaxDynamicSharedMemorySize, DS);

    // 1) shift + zigzag gather with fused f16 convert
    {
        int total = BB * TT * (CC / 4);
        shift_gather_kernel<<<(total + 255) / 256, 256>>>(x, xs);
    }
    // weight converts (single launch)
    {
        int total = CC * CC;           // 4 * CC*CC/4
        wconv4_kernel<<<(total + 255) / 256, 256>>>(kw, vw, rw, ow, wh);
    }

    // 2) k (f32 out), v (f16), sr (f16 + sigmoid)
    {
        dim3 grid(CC / 128, MM / 128);
        gemm_fp16_kernel<0, float ><<<grid, 256, DS>>>(xs, wh + 0 * (size_t)CC * CC, k);
        gemm_fp16_kernel<0, __half><<<grid, 256, DS>>>(xs, wh + 1 * (size_t)CC * CC, v);
        gemm_fp16_kernel<1, __half><<<grid, 256, DS>>>(xs, wh + 2 * (size_t)CC * CC, sr);
    }

    // 3) WKV pass 1 (t order) then pass 2 (zigzag involution order)
    {
        dim3 gseg(LANES / 128, NSEG);
        int  gscan = LANES / 128;
        wkv_summary_kernel<0><<<gseg, 128>>>(k, v, sdec);
        wkv_scan_kernel<0><<<gscan, 128>>>(sdec);
        wkv_replay_kernel<0><<<gseg, 128>>>(k, v, sdec, sfst, v1);

        wkv_summary_kernel<1><<<gseg, 128>>>(k, v1, sdec);
        wkv_scan_kernel<1><<<gscan, 128>>>(sdec);
        wkv_replay_kernel<1><<<gseg, 128>>>(k, v1, sdec, sfst, vf);
    }

    // 4) out = (sr .* vf) @ ow^T
    {
        int total = ELEMS / 8;
        ewmul_kernel<<<(total + 255) / 256, 256>>>(sr, vf, prod);
        dim3 grid(CC / 128, MM / 128);
        gemm_fp16_kernel<0, float><<<grid, 256, DS>>>(prod, wh + 3 * (size_t)CC * CC, out);
    }
}